// round 16
// baseline (speedup 1.0000x reference)
#include <cuda_runtime.h>
#include <cstdint>

// out[i,j,k] = sum_d x[1+i,d] * x[1+j,d] * Wp[d,k] + b[k]   (symmetric in i,j)
// X: [512,1280] f32, Wp = W[:1280] of W:[2560,2], out: [510,510,2] f32.
//
// Two kernels:
//  1) contact_sym_kernel: 128-thread CTAs, triangular 64x64 tiles (ti>=tj),
//     D split into 8 z-slices. Thread tile 8i x 4j x 2k (2B moved per FFMA2
//     -> crossbar == fma roofline). Fill: coalesced LDG + in-register W
//     scaling + conflict-free transposed STS, register double-buffered.
//  2) reduce_kernel: 512 CTAs, slice sum + mirror transpose + bias.

namespace {

constexpr int Dd   = 1280;
constexpr int ON   = 510;
constexpr int TS   = 64;              // tile size
constexpr int KT   = 16;              // d per chunk
constexpr int SSTR = 68;              // smem row stride
constexpr int ZS   = 8;               // D slices (160 d each)
constexpr int DPZ  = Dd / ZS;
constexpr int NCH  = DPZ / KT;        // 10 chunks per slice
constexpr int NT   = 36;              // triangular tiles over 8x8
constexpr int TILE_ELEMS = TS * TS * 2;

__device__ float g_part[(size_t)ZS * NT * TILE_ELEMS];   // 9.4 MB partials

__device__ __forceinline__ void fma2(unsigned long long& acc,
                                     unsigned long long a,
                                     unsigned long long b) {
    asm("fma.rn.f32x2 %0, %1, %2, %0;" : "+l"(acc) : "l"(a), "l"(b));
}

__device__ __forceinline__ unsigned long long dup2(float v) {
    unsigned long long r;
    unsigned int u = __float_as_uint(v);
    asm("mov.b64 %0, {%1, %1};" : "=l"(r) : "r"(u));
    return r;
}

// ---------------- main symmetric GEMM, 128 threads, 8x4x2 thread tile -------
__global__ __launch_bounds__(128, 2)
void contact_sym_kernel(const float* __restrict__ x, const float* __restrict__ W)
{
    __shared__ float smA [2][KT][SSTR];
    __shared__ float smB0[2][KT][SSTR];
    __shared__ float smB1[2][KT][SSTR];

    const int tid  = threadIdx.x;
    const int lane = tid & 31;
    const int w    = tid >> 5;                  // 0..3
    // warp owns 32i x 32j: per-warp-d unique LDS = 128(A)+128(B0)+128(B1)
    const int ty = (w & 1) * 4 + (lane & 3);    // i group (0..7), 8 i each
    const int tx = (w >> 1) * 8 + (lane >> 2);  // j group (0..15), 4 j each

    // decode triangular tile id -> (ti, tj), ti >= tj
    int rem = blockIdx.x, ti = 0;
    while (rem > ti) { rem -= (ti + 1); ti++; }
    const int tj = rem;
    const int z  = blockIdx.y;

    const int ibase = ti * TS;
    const int jbase = tj * TS;
    const int dbase = z * DPZ;

    // fill mapping: fr = row in tile (0..63), dq = d offset (0 or 8)
    const int fr = tid & 63;
    const int dq = (tid >> 6) * 8;

    const int gi = ibase + fr;
    const int gj = jbase + fr;
    const bool vi = (gi < 511);           // x row gi+1 valid
    const bool vj = (gj < 511);

    const float* __restrict__ xa = x + (size_t)(gi + 1) * Dd + dbase + dq;
    const float* __restrict__ xb = x + (size_t)(gj + 1) * Dd + dbase + dq;
    const float4* __restrict__ wp = reinterpret_cast<const float4*>(W + 2 * (dbase + dq));
    // wp[c*8 .. c*8+3] = W pairs for the 8 d-values of chunk c at this dq

    unsigned long long acc[2][8][2];
    #pragma unroll
    for (int k = 0; k < 2; ++k)
        #pragma unroll
        for (int ii = 0; ii < 8; ++ii)
            #pragma unroll
            for (int jp = 0; jp < 2; ++jp)
                acc[k][ii][jp] = 0ull;

    float4 rA0, rA1, rB0, rB1, rW0, rW1, rW2, rW3;

    auto load_regs = [&](int c) {
        const size_t off = (size_t)c * KT;
        if (vi) {
            rA0 = *reinterpret_cast<const float4*>(xa + off);
            rA1 = *reinterpret_cast<const float4*>(xa + off + 4);
        } else { rA0 = rA1 = make_float4(0,0,0,0); }
        if (vj) {
            rB0 = *reinterpret_cast<const float4*>(xb + off);
            rB1 = *reinterpret_cast<const float4*>(xb + off + 4);
        } else { rB0 = rB1 = make_float4(0,0,0,0); }
        const float4* wc = wp + (size_t)c * (KT / 2);  // KT d -> KT float2 -> KT/2 float4 per dq-half
        rW0 = wc[0]; rW1 = wc[1]; rW2 = wc[2]; rW3 = wc[3];
    };

    auto store_tiles = [&](int nb) {
        smA [nb][dq + 0][fr] = rA0.x;
        smA [nb][dq + 1][fr] = rA0.y;
        smA [nb][dq + 2][fr] = rA0.z;
        smA [nb][dq + 3][fr] = rA0.w;
        smA [nb][dq + 4][fr] = rA1.x;
        smA [nb][dq + 5][fr] = rA1.y;
        smA [nb][dq + 6][fr] = rA1.z;
        smA [nb][dq + 7][fr] = rA1.w;
        smB0[nb][dq + 0][fr] = rB0.x * rW0.x;  smB1[nb][dq + 0][fr] = rB0.x * rW0.y;
        smB0[nb][dq + 1][fr] = rB0.y * rW0.z;  smB1[nb][dq + 1][fr] = rB0.y * rW0.w;
        smB0[nb][dq + 2][fr] = rB0.z * rW1.x;  smB1[nb][dq + 2][fr] = rB0.z * rW1.y;
        smB0[nb][dq + 3][fr] = rB0.w * rW1.z;  smB1[nb][dq + 3][fr] = rB0.w * rW1.w;
        smB0[nb][dq + 4][fr] = rB1.x * rW2.x;  smB1[nb][dq + 4][fr] = rB1.x * rW2.y;
        smB0[nb][dq + 5][fr] = rB1.y * rW2.z;  smB1[nb][dq + 5][fr] = rB1.y * rW2.w;
        smB0[nb][dq + 6][fr] = rB1.z * rW3.x;  smB1[nb][dq + 6][fr] = rB1.z * rW3.y;
        smB0[nb][dq + 7][fr] = rB1.w * rW3.z;  smB1[nb][dq + 7][fr] = rB1.w * rW3.w;
    };

    // prologue: chunk 0 -> buffer 0
    load_regs(0);
    store_tiles(0);
    __syncthreads();

    for (int c = 0; c < NCH; ++c) {
        const bool more = (c + 1 < NCH);
        if (more) load_regs(c + 1);

        const int cb = c & 1;
        #pragma unroll
        for (int d = 0; d < KT; ++d) {
            float4 aLo = *reinterpret_cast<const float4*>(&smA[cb][d][8 * ty]);
            float4 aHi = *reinterpret_cast<const float4*>(&smA[cb][d][8 * ty + 4]);
            unsigned long long A[8];
            A[0] = dup2(aLo.x); A[1] = dup2(aLo.y);
            A[2] = dup2(aLo.z); A[3] = dup2(aLo.w);
            A[4] = dup2(aHi.x); A[5] = dup2(aHi.y);
            A[6] = dup2(aHi.z); A[7] = dup2(aHi.w);

            ulonglong2 B0 = *reinterpret_cast<const ulonglong2*>(&smB0[cb][d][4 * tx]);
            ulonglong2 B1 = *reinterpret_cast<const ulonglong2*>(&smB1[cb][d][4 * tx]);

            #pragma unroll
            for (int ii = 0; ii < 8; ++ii) {
                fma2(acc[0][ii][0], A[ii], B0.x);
                fma2(acc[0][ii][1], A[ii], B0.y);
                fma2(acc[1][ii][0], A[ii], B1.x);
                fma2(acc[1][ii][1], A[ii], B1.y);
            }
        }

        if (more) {
            const int nb = cb ^ 1;
            store_tiles(nb);
            __syncthreads();
        }
    }

    // epilogue: partials to scratch, k-interleaved [li][lj][k]
    float* __restrict__ s = g_part + ((size_t)z * NT + blockIdx.x) * TILE_ELEMS;
    const int lj0 = 4 * tx;
    #pragma unroll
    for (int ii = 0; ii < 8; ++ii) {
        const int li = 8 * ty + ii;
        #pragma unroll
        for (int jp = 0; jp < 2; ++jp) {
            unsigned int k0e, k0o, k1e, k1o;
            asm("mov.b64 {%0, %1}, %2;" : "=r"(k0e), "=r"(k0o) : "l"(acc[0][ii][jp]));
            asm("mov.b64 {%0, %1}, %2;" : "=r"(k1e), "=r"(k1o) : "l"(acc[1][ii][jp]));
            float4 v = make_float4(__uint_as_float(k0e), __uint_as_float(k1e),
                                   __uint_as_float(k0o), __uint_as_float(k1o));
            *reinterpret_cast<float4*>(&s[((size_t)li * TS + lj0 + 2 * jp) * 2]) = v;
        }
    }
}

// ---------------- reduce: 512 CTAs, slice sum + mirror + bias ----------------
// grid = (8 slices of 8 rows, 64 output tiles); block = 256 threads.
__global__ __launch_bounds__(256)
void reduce_kernel(const float* __restrict__ bvec, float* __restrict__ out)
{
    __shared__ float2 sm[8][67];     // padded transpose buffer (mirror path)

    const int t   = threadIdx.x;
    const int h   = blockIdx.x;            // 0..7: 8-row slice
    const int ot  = blockIdx.y;            // output tile id
    const int oti = ot >> 3;
    const int otj = ot & 7;

    const float b0 = bvec[0];
    const float b1 = bvec[1];

    if (oti >= otj) {
        const int src = (oti * (oti + 1)) / 2 + otj;
        const float* base = g_part + (size_t)src * TILE_ELEMS;
        int a  = h * 8 + (t >> 5);            // row li
        int lj = (t & 31) * 2;                // col pair
        size_t off = ((size_t)a * TS + lj) * 2;

        float4 acc = make_float4(b0, b1, b0, b1);
        #pragma unroll
        for (int z = 0; z < ZS; ++z) {
            float4 v = *reinterpret_cast<const float4*>(
                base + (size_t)z * NT * TILE_ELEMS + off);
            acc.x += v.x; acc.y += v.y; acc.z += v.z; acc.w += v.w;
        }
        int i = oti * TS + a;
        int j = otj * TS + lj;
        if (i < ON && j < ON)
            *reinterpret_cast<float4*>(&out[((size_t)i * ON + j) * 2]) = acc;
    } else {
        // mirror: source tile (otj,oti); out[li][lj] = src[lj][li]
        const int src = (otj * (otj + 1)) / 2 + oti;
        const float* base = g_part + (size_t)src * TILE_ELEMS;
        int b  = t >> 2;                      // src row (= out col lj), 0..63
        int c  = t & 3;                       // col-pair group within slice
        int a0 = h * 8 + c * 2;               // src cols (= out rows li)
        size_t off = ((size_t)b * TS + a0) * 2;

        float4 acc = make_float4(b0, b1, b0, b1);
        #pragma unroll
        for (int z = 0; z < ZS; ++z) {
            float4 v = *reinterpret_cast<const float4*>(
                base + (size_t)z * NT * TILE_ELEMS + off);
            acc.x += v.x; acc.y += v.y; acc.z += v.z; acc.w += v.w;
        }
        sm[c * 2 + 0][b] = make_float2(acc.x, acc.y);
        sm[c * 2 + 1][b] = make_float2(acc.z, acc.w);
        __syncthreads();

        // coalesced write-out: row li_loc = t/32, 1 float4 per thread along lj
        const int li_loc = t >> 5;            // 0..7
        const int fq     = t & 31;
        const int i      = oti * TS + h * 8 + li_loc;
        int lj = fq * 2;
        int j  = otj * TS + lj;
        if (i < ON && j < ON) {
            float2 e0 = sm[li_loc][lj];
            float2 e1 = sm[li_loc][lj + 1];
            *reinterpret_cast<float4*>(&out[((size_t)i * ON + j) * 2]) =
                make_float4(e0.x, e0.y, e1.x, e1.y);
        }
    }
}

} // namespace

extern "C" void kernel_launch(void* const* d_in, const int* in_sizes, int n_in,
                              void* d_out, int out_size)
{
    const float* x = nullptr;
    const float* W = nullptr;
    const float* b = nullptr;
    for (int i = 0; i < n_in; ++i) {
        if (in_sizes[i] == 512 * 1280)      x = (const float*)d_in[i];
        else if (in_sizes[i] == 2560 * 2)   W = (const float*)d_in[i];
        else if (in_sizes[i] == 2)          b = (const float*)d_in[i];
    }

    contact_sym_kernel<<<dim3(NT, ZS), 128>>>(x, W);     // 288 CTAs
    reduce_kernel<<<dim3(8, 64), 256>>>(b, (float*)d_out);
}